// round 1
// baseline (speedup 1.0000x reference)
#include <cuda_runtime.h>

// ---------------- problem constants ----------------
#define BQ 16
#define HQ 256
#define SQ 16
#define NLEAF 15625
#define NINT 3906

#define TM 64
#define TN 128
#define TK 16

// ---------------- static device scratch ----------------
__device__ float g_featA[BQ * NLEAF * HQ];          // 256 MB
__device__ float g_featB[BQ * 3125 * HQ];           // 51 MB
__device__ int   g_perm[63648];                     // per-level padded permutations
__device__ int   g_count[18];
__device__ int   g_cursor[18];
__device__ int   g_seg[24];                         // [l][0..2]=padded seg starts, [l][3]=padded total

__constant__ int c_n[6]     = {1, 5, 25, 125, 625, 3125};
__constant__ int c_off[6]   = {0, 1, 6, 31, 156, 781};
__constant__ int c_cumM[7]  = {0, 16, 96, 496, 2496, 12496, 62496};
__constant__ int c_pbase[6] = {0, 208, 480, 1072, 3264, 13456};

// ---------------- prep kernels ----------------
__global__ void k_reset() {
    int i = blockIdx.x * blockDim.x + threadIdx.x;
    if (i < 63648) g_perm[i] = -1;
    if (i < 18) { g_count[i] = 0; g_cursor[i] = 0; }
}

__device__ __forceinline__ void decode_row(int r, int& l, int& pr, int& b, int& j) {
    l = 0;
    while (r >= c_cumM[l + 1]) l++;
    pr = r - c_cumM[l];
    int n = c_n[l];
    b = pr / n;
    j = pr - b * n;
}

__global__ void k_count(const int* __restrict__ nt) {
    int r = blockIdx.x * blockDim.x + threadIdx.x;
    if (r >= 62496) return;
    int l, pr, b, j;
    decode_row(r, l, pr, b, j);
    int t = nt[b * NINT + c_off[l] + j];
    atomicAdd(&g_count[l * 3 + t], 1);
}

__global__ void k_scan() {
    if (blockIdx.x == 0 && threadIdx.x == 0) {
        for (int l = 0; l < 6; l++) {
            int base = 0;
            for (int t = 0; t < 3; t++) {
                g_seg[l * 4 + t] = base;
                base += ((g_count[l * 3 + t] + TM - 1) / TM) * TM;
            }
            g_seg[l * 4 + 3] = base;
        }
    }
}

__global__ void k_scatter(const int* __restrict__ nt) {
    int r = blockIdx.x * blockDim.x + threadIdx.x;
    if (r >= 62496) return;
    int l, pr, b, j;
    decode_row(r, l, pr, b, j);
    int t = nt[b * NINT + c_off[l] + j];
    int pos = g_seg[l * 4 + t] + atomicAdd(&g_cursor[l * 3 + t], 1);
    g_perm[c_pbase[l] + pos] = pr;
}

// ---------------- leaf encoder ----------------
// feats[row,h] = relu(box@Wb+bb) + relu(sem@Ws+bs), row in [0, B*NLEAF)
__global__ void k_leaf(const float* __restrict__ lbox, const float* __restrict__ lsem,
                       const float* __restrict__ Wb, const float* __restrict__ bb,
                       const float* __restrict__ Ws, const float* __restrict__ bs) {
    int row = blockIdx.x;
    int h = threadIdx.x;
    __shared__ float sb[4];
    __shared__ float ss[16];
    if (h < 4)  sb[h] = lbox[(long)row * 4 + h];
    if (h < 16) ss[h] = lsem[(long)row * 16 + h];
    __syncthreads();
    float a = bb[h];
#pragma unroll
    for (int q = 0; q < 4; q++) a = fmaf(sb[q], Wb[q * HQ + h], a);
    float v = fmaxf(a, 0.f);
    float a2 = bs[h];
#pragma unroll
    for (int s = 0; s < 16; s++) a2 = fmaf(ss[s], Ws[s * HQ + h], a2);
    v += fmaxf(a2, 0.f);
    g_featA[(long)row * HQ + h] = v;
}

// ---------------- per-level grouped GEMM ----------------
// A row pr (permuted): contiguous 1280 floats at src + 1280*pr (the 5 children).
// Y[pr, h] = relu(A[pr] @ W_node[t] + b_node[t]) + relu(ibox @ W_box + b_box)
__global__ __launch_bounds__(128) void k_gemm(
    int srcA, int lvl, int n, int off,
    const float* __restrict__ ibox, const float* __restrict__ Wn,
    const float* __restrict__ bn, const float* __restrict__ Wb,
    const float* __restrict__ bb) {

    const float* __restrict__ src = srcA ? g_featA : g_featB;
    float* __restrict__ dst = srcA ? g_featB : g_featA;

    __shared__ float As[TK][TM];
    __shared__ float Bs[TK][TN];
    __shared__ int   s_pr[TM];
    __shared__ float s_wbox[4][TN];
    __shared__ float s_bbox[TN];
    __shared__ float s_bnode[TN];

    int m0 = blockIdx.y * TM;
    int total = g_seg[lvl * 4 + 3];
    if (m0 >= total) return;
    int t = (m0 >= g_seg[lvl * 4 + 2]) ? 2 : (m0 >= g_seg[lvl * 4 + 1]) ? 1 : 0;
    int n0 = blockIdx.x * TN;
    int tid = threadIdx.x;

    if (tid < TM) s_pr[tid] = g_perm[c_pbase[lvl] + m0 + tid];
    for (int i = tid; i < 4 * TN; i += 128) {
        int q = i / TN, c = i - q * TN;
        s_wbox[q][c] = Wb[q * HQ + n0 + c];
    }
    s_bbox[tid] = bb[n0 + tid];
    s_bnode[tid] = bn[t * HQ + n0 + tid];
    __syncthreads();

    const float* __restrict__ wbase = Wn + (size_t)t * 1280 * HQ + n0;

    int tx = tid & 15;   // N dir
    int ty = tid >> 4;   // M dir

    // A load mapping: 64 rows x 16 k = 2 float4 per thread
    int am = tid >> 1;
    int af = tid & 1;
    long abase = (s_pr[am] >= 0) ? (long)s_pr[am] * 1280 : -1;

    // B load mapping: 16 k x 128 n = 4 float4 per thread
    int bk = tid >> 3;   // 0..15
    int bc = tid & 7;    // 0..7

    float acc[8][8];
#pragma unroll
    for (int i = 0; i < 8; i++)
#pragma unroll
        for (int j = 0; j < 8; j++) acc[i][j] = 0.f;

    float4 ra0, ra1, rb[4];
    // prefetch k0 = 0
    if (abase >= 0) {
        ra0 = *(const float4*)(src + abase + af * 8);
        ra1 = *(const float4*)(src + abase + af * 8 + 4);
    } else {
        ra0 = make_float4(0, 0, 0, 0);
        ra1 = make_float4(0, 0, 0, 0);
    }
#pragma unroll
    for (int q = 0; q < 4; q++)
        rb[q] = *(const float4*)(wbase + (size_t)bk * HQ + (bc + 8 * q) * 4);

    for (int k0 = 0; k0 < 1280; k0 += TK) {
        __syncthreads();
        // store current tile
        As[af * 8 + 0][am] = ra0.x;
        As[af * 8 + 1][am] = ra0.y;
        As[af * 8 + 2][am] = ra0.z;
        As[af * 8 + 3][am] = ra0.w;
        As[af * 8 + 4][am] = ra1.x;
        As[af * 8 + 5][am] = ra1.y;
        As[af * 8 + 6][am] = ra1.z;
        As[af * 8 + 7][am] = ra1.w;
#pragma unroll
        for (int q = 0; q < 4; q++)
            *(float4*)&Bs[bk][(bc + 8 * q) * 4] = rb[q];
        __syncthreads();

        // prefetch next tile
        int k1 = k0 + TK;
        if (k1 < 1280) {
            if (abase >= 0) {
                ra0 = *(const float4*)(src + abase + k1 + af * 8);
                ra1 = *(const float4*)(src + abase + k1 + af * 8 + 4);
            }
#pragma unroll
            for (int q = 0; q < 4; q++)
                rb[q] = *(const float4*)(wbase + (size_t)(k1 + bk) * HQ + (bc + 8 * q) * 4);
        }

        // compute
#pragma unroll
        for (int k = 0; k < TK; k++) {
            float4 a0 = *(float4*)&As[k][ty * 4];
            float4 a1 = *(float4*)&As[k][32 + ty * 4];
            float4 b0 = *(float4*)&Bs[k][tx * 4];
            float4 b1 = *(float4*)&Bs[k][64 + tx * 4];
            float ar[8] = {a0.x, a0.y, a0.z, a0.w, a1.x, a1.y, a1.z, a1.w};
            float br[8] = {b0.x, b0.y, b0.z, b0.w, b1.x, b1.y, b1.z, b1.w};
#pragma unroll
            for (int i = 0; i < 8; i++)
#pragma unroll
                for (int j = 0; j < 8; j++)
                    acc[i][j] = fmaf(ar[i], br[j], acc[i][j]);
        }
    }

    // epilogue
#pragma unroll
    for (int i = 0; i < 8; i++) {
        int rm = (i < 4) ? (ty * 4 + i) : (32 + ty * 4 + (i - 4));
        int pr = s_pr[rm];
        if (pr < 0) continue;
        int b = pr / n;
        int j = pr - b * n;
        const float* bxp = ibox + ((long)b * NINT + off + j) * 4;
        float bx0 = bxp[0], bx1 = bxp[1], bx2 = bxp[2], bx3 = bxp[3];
        float o[8];
#pragma unroll
        for (int jj = 0; jj < 8; jj++) {
            int c = (jj < 4) ? (tx * 4 + jj) : (64 + tx * 4 + (jj - 4));
            float be = s_bbox[c];
            be = fmaf(bx0, s_wbox[0][c], be);
            be = fmaf(bx1, s_wbox[1][c], be);
            be = fmaf(bx2, s_wbox[2][c], be);
            be = fmaf(bx3, s_wbox[3][c], be);
            o[jj] = fmaxf(acc[i][jj] + s_bnode[c], 0.f) + fmaxf(be, 0.f);
        }
        float* drow = dst + (long)pr * HQ + n0;
        *(float4*)(drow + tx * 4)      = make_float4(o[0], o[1], o[2], o[3]);
        *(float4*)(drow + 64 + tx * 4) = make_float4(o[4], o[5], o[6], o[7]);
    }
}

// ---------------- VAE head ----------------
__global__ void k_head(const float* __restrict__ eps,
                       const float* __restrict__ W1, const float* __restrict__ b1,
                       const float* __restrict__ Wmu, const float* __restrict__ bmu,
                       const float* __restrict__ Wvar, const float* __restrict__ bvar,
                       float* __restrict__ out) {
    int b = blockIdx.x;
    int h = threadIdx.x;
    __shared__ float sroot[HQ];
    __shared__ float senc[HQ];
    sroot[h] = g_featA[b * HQ + h];
    __syncthreads();
    float a = b1[h];
    for (int k = 0; k < HQ; k++) a = fmaf(sroot[k], W1[k * HQ + h], a);
    senc[h] = fmaxf(a, 0.f);
    __syncthreads();
    float mu = bmu[h], lv = bvar[h];
    for (int k = 0; k < HQ; k++) {
        float e = senc[k];
        mu = fmaf(e, Wmu[k * HQ + h], mu);
        lv = fmaf(e, Wvar[k * HQ + h], lv);
    }
    float stdv = expf(0.5f * lv);
    out[b * 2 * HQ + h] = eps[b * HQ + h] * stdv + mu;
    out[b * 2 * HQ + HQ + h] = 1.f + lv - mu * mu - expf(lv);
}

// ---------------- launch ----------------
extern "C" void kernel_launch(void* const* d_in, const int* in_sizes, int n_in,
                              void* d_out, int out_size) {
    const float* leaf_box     = (const float*)d_in[0];
    const float* leaf_sem     = (const float*)d_in[1];
    const float* internal_box = (const float*)d_in[2];
    const int*   node_type    = (const int*)d_in[3];
    const float* eps          = (const float*)d_in[4];
    const float* W_box        = (const float*)d_in[5];
    const float* b_box        = (const float*)d_in[6];
    const float* W_sem        = (const float*)d_in[7];
    const float* b_sem        = (const float*)d_in[8];
    const float* W_node       = (const float*)d_in[9];
    const float* b_node       = (const float*)d_in[10];
    const float* W1           = (const float*)d_in[11];
    const float* b1           = (const float*)d_in[12];
    const float* Wmu          = (const float*)d_in[13];
    const float* bmu          = (const float*)d_in[14];
    const float* Wvar         = (const float*)d_in[15];
    const float* bvar         = (const float*)d_in[16];
    float* out = (float*)d_out;

    k_reset<<<(63648 + 255) / 256, 256>>>();
    k_count<<<(62496 + 255) / 256, 256>>>(node_type);
    k_scan<<<1, 1>>>();
    k_scatter<<<(62496 + 255) / 256, 256>>>(node_type);
    k_leaf<<<BQ * NLEAF, HQ>>>(leaf_box, leaf_sem, W_box, b_box, W_sem, b_sem);

    // level l: (srcA flag, n, off, gridY = ceil(M/TM)+3)
    // ping-pong: A->B->A->B->A->B->A
    struct Lv { int srcA, lvl, n, off, gy; };
    const Lv lv[6] = {
        {1, 5, 3125, 781, 785},
        {0, 4,  625, 156, 160},
        {1, 3,  125,  31,  35},
        {0, 2,   25,   6,  10},
        {1, 1,    5,   1,   5},
        {0, 0,    1,   0,   4},
    };
    for (int i = 0; i < 6; i++) {
        dim3 grid(HQ / TN, lv[i].gy);
        k_gemm<<<grid, 128>>>(lv[i].srcA, lv[i].lvl, lv[i].n, lv[i].off,
                              internal_box, W_node, b_node, W_box, b_box);
    }

    k_head<<<BQ, HQ>>>(eps, W1, b1, Wmu, bmu, Wvar, bvar, out);
}

// round 3
// speedup vs baseline: 1.8370x; 1.8370x over previous
#include <cuda_runtime.h>
#include <cuda_bf16.h>
#include <cstdint>

// ---------------- problem constants ----------------
#define BQ 16
#define HQ 256
#define NLEAF 15625
#define NINT 3906
#define TMG 128          // GEMM M tile
#define TNG 128          // GEMM N tile
#define KC 64            // K per stage
#define NSTAGE 20        // 1280/64
#define STAGE_BYTES 65536
#define SMEM_BYTES (4096 + 3 * STAGE_BYTES)

// ---------------- static device scratch ----------------
__device__ __nv_bfloat16 g_hiA[(size_t)BQ * NLEAF * HQ];
__device__ __nv_bfloat16 g_loA[(size_t)BQ * NLEAF * HQ];
__device__ __nv_bfloat16 g_hiB[BQ * 3125 * HQ];
__device__ __nv_bfloat16 g_loB[BQ * 3125 * HQ];
__device__ __nv_bfloat16 g_WThi[3 * HQ * 1280];   // [t][n][k]
__device__ __nv_bfloat16 g_WTlo[3 * HQ * 1280];
__device__ int g_perm[65536];
__device__ int g_count[18];
__device__ int g_cursor[18];
__device__ int g_seg[24];

__constant__ int c_n[6]     = {1, 5, 25, 125, 625, 3125};
__constant__ int c_off[6]   = {0, 1, 6, 31, 156, 781};
__constant__ int c_cumM[7]  = {0, 16, 96, 496, 2496, 12496, 62496};
__constant__ int c_pbase[6] = {0, 512, 1024, 2048, 4608, 15104};

// ---------------- helpers ----------------
__device__ __forceinline__ uint32_t smem_u32(const void* p) {
    uint32_t a;
    asm("{ .reg .u64 t; cvta.to.shared.u64 t, %1; cvt.u32.u64 %0, t; }" : "=r"(a) : "l"(p));
    return a;
}
#define SWZ(x) ((x) ^ (((x) >> 3) & 0x70))

#define CP16(d, s)  asm volatile("cp.async.cg.shared.global [%0], [%1], 16;" :: "r"(d), "l"(s) : "memory")
#define CP_COMMIT() asm volatile("cp.async.commit_group;" ::: "memory")
#define CP_WAIT2()  asm volatile("cp.async.wait_group 2;" ::: "memory")

__device__ __forceinline__ void ldm4(uint32_t addr, uint32_t* r) {
    asm volatile("ldmatrix.sync.aligned.m8n8.x4.shared.b16 {%0,%1,%2,%3}, [%4];"
                 : "=r"(r[0]), "=r"(r[1]), "=r"(r[2]), "=r"(r[3]) : "r"(addr));
}
__device__ __forceinline__ void mma16816(float* c, const uint32_t* a, const uint32_t* b) {
    asm volatile(
        "mma.sync.aligned.m16n8k16.row.col.f32.bf16.bf16.f32 "
        "{%0,%1,%2,%3}, {%4,%5,%6,%7}, {%8,%9}, {%0,%1,%2,%3};"
        : "+f"(c[0]), "+f"(c[1]), "+f"(c[2]), "+f"(c[3])
        : "r"(a[0]), "r"(a[1]), "r"(a[2]), "r"(a[3]), "r"(b[0]), "r"(b[1]));
}
__device__ __forceinline__ void split2(float x, __nv_bfloat16& h, __nv_bfloat16& l) {
    h = __float2bfloat16(x);
    l = __float2bfloat16(x - __bfloat162float(h));
}

// ---------------- prep kernels ----------------
__global__ void k_reset() {
    int i = blockIdx.x * blockDim.x + threadIdx.x;
    if (i < 65536) g_perm[i] = -1;
    if (i < 18) { g_count[i] = 0; g_cursor[i] = 0; }
}

__device__ __forceinline__ void decode_row(int r, int& l, int& pr, int& b, int& j) {
    l = 0;
    while (r >= c_cumM[l + 1]) l++;
    pr = r - c_cumM[l];
    int n = c_n[l];
    b = pr / n;
    j = pr - b * n;
}

__global__ void k_count(const int* __restrict__ nt) {
    __shared__ int sc[18];
    int tid = threadIdx.x;
    if (tid < 18) sc[tid] = 0;
    __syncthreads();
    int r = blockIdx.x * blockDim.x + tid;
    if (r < 62496) {
        int l, pr, b, j;
        decode_row(r, l, pr, b, j);
        int t = nt[b * NINT + c_off[l] + j];
        atomicAdd(&sc[l * 3 + t], 1);
    }
    __syncthreads();
    if (tid < 18 && sc[tid]) atomicAdd(&g_count[tid], sc[tid]);
}

__global__ void k_scan() {
    if (threadIdx.x == 0) {
        for (int l = 0; l < 6; l++) {
            int base = 0;
            for (int t = 0; t < 3; t++) {
                g_seg[l * 4 + t] = base;
                base += ((g_count[l * 3 + t] + TMG - 1) / TMG) * TMG;
            }
            g_seg[l * 4 + 3] = base;
        }
    }
}

__global__ void k_scatter(const int* __restrict__ nt) {
    __shared__ int sc[18], sbase[18];
    int tid = threadIdx.x;
    if (tid < 18) sc[tid] = 0;
    __syncthreads();
    int r = blockIdx.x * blockDim.x + tid;
    int lt = -1, lpos = 0, l = 0, pr = 0;
    if (r < 62496) {
        int b, j;
        decode_row(r, l, pr, b, j);
        int t = nt[b * NINT + c_off[l] + j];
        lt = l * 3 + t;
        lpos = atomicAdd(&sc[lt], 1);
    }
    __syncthreads();
    if (tid < 18 && sc[tid]) sbase[tid] = atomicAdd(&g_cursor[tid], sc[tid]);
    __syncthreads();
    if (lt >= 0) {
        int t = lt - l * 3;
        g_perm[c_pbase[l] + g_seg[l * 4 + t] + sbase[lt] + lpos] = pr;
    }
}

// W_node (3,1280,256) -> [t][n][k] split bf16
__global__ void k_wt(const float* __restrict__ Wn) {
    int i = blockIdx.x * blockDim.x + threadIdx.x;
    if (i >= 3 * HQ * 1280) return;
    int k = i % 1280;
    int r = i / 1280;
    int nn = r % HQ;
    int t = r / HQ;
    float x = Wn[((size_t)t * 1280 + k) * HQ + nn];
    __nv_bfloat16 h, l;
    split2(x, h, l);
    g_WThi[i] = h;
    g_WTlo[i] = l;
}

// ---------------- leaf encoder ----------------
__global__ __launch_bounds__(256) void k_leaf(
    const float* __restrict__ lbox, const float* __restrict__ lsem,
    const float* __restrict__ Wb, const float* __restrict__ bb,
    const float* __restrict__ Ws, const float* __restrict__ bs) {
    __shared__ float sbox[4][4];
    __shared__ float ssem[4][16];
    int tid = threadIdx.x;
    long row0 = (long)blockIdx.x * 4;
    if (tid < 16) sbox[tid >> 2][tid & 3] = lbox[row0 * 4 + tid];
    if (tid < 64) ssem[tid >> 4][tid & 15] = lsem[row0 * 16 + tid];
    __syncthreads();
    int r = tid >> 6;
    int c = (tid & 63) * 4;
    long row = row0 + r;
    float4 a = *(const float4*)(bb + c);
    float acc[4] = {a.x, a.y, a.z, a.w};
#pragma unroll
    for (int q = 0; q < 4; q++) {
        float4 w = *(const float4*)(Wb + q * HQ + c);
        float x = sbox[r][q];
        acc[0] = fmaf(x, w.x, acc[0]); acc[1] = fmaf(x, w.y, acc[1]);
        acc[2] = fmaf(x, w.z, acc[2]); acc[3] = fmaf(x, w.w, acc[3]);
    }
    float4 a2 = *(const float4*)(bs + c);
    float acs[4] = {a2.x, a2.y, a2.z, a2.w};
#pragma unroll
    for (int q = 0; q < 16; q++) {
        float4 w = *(const float4*)(Ws + q * HQ + c);
        float x = ssem[r][q];
        acs[0] = fmaf(x, w.x, acs[0]); acs[1] = fmaf(x, w.y, acs[1]);
        acs[2] = fmaf(x, w.z, acs[2]); acs[3] = fmaf(x, w.w, acs[3]);
    }
    uint32_t hp[2], lp[2];
#pragma unroll
    for (int i = 0; i < 4; i += 2) {
        __nv_bfloat16 h0, l0, h1, l1;
        float v0 = fmaxf(acc[i], 0.f) + fmaxf(acs[i], 0.f);
        float v1 = fmaxf(acc[i + 1], 0.f) + fmaxf(acs[i + 1], 0.f);
        split2(v0, h0, l0);
        split2(v1, h1, l1);
        hp[i >> 1] = (uint32_t)__bfloat16_as_ushort(h0) | ((uint32_t)__bfloat16_as_ushort(h1) << 16);
        lp[i >> 1] = (uint32_t)__bfloat16_as_ushort(l0) | ((uint32_t)__bfloat16_as_ushort(l1) << 16);
    }
    *(uint2*)(g_hiA + row * HQ + c) = make_uint2(hp[0], hp[1]);
    *(uint2*)(g_loA + row * HQ + c) = make_uint2(lp[0], lp[1]);
}

// ---------------- mma.sync grouped GEMM ----------------
// smem: 0 s_pr[128] | 512 s_ab[128] | 1024 wbox[4*128]f | 3072 bbox[128]f |
//       3584 bnode[128]f | 4096 + stg*64K: {Ahi 16K | Alo 16K | Bhi 16K | Blo 16K}
__device__ __forceinline__ void load_stage(
    uint32_t sb, int stg, int k0, int t, int n0, int tid,
    const __nv_bfloat16* __restrict__ srcHi, const __nv_bfloat16* __restrict__ srcLo,
    const int* __restrict__ s_ab) {
    uint32_t base = sb + 4096 + stg * STAGE_BYTES;
#pragma unroll
    for (int i = 0; i < 8; i++) {          // A: 2048 chunks of 16B
        int it = tid + i * 256;
        int split = it >> 10;
        int row = (it >> 3) & 127;
        int ch = it & 7;
        const __nv_bfloat16* sp = (split ? srcLo : srcHi) + (size_t)s_ab[row] + k0 + ch * 8;
        uint32_t off = (uint32_t)(row * 128 + ch * 16);
        CP16(base + split * 16384 + SWZ(off), sp);
    }
    const __nv_bfloat16* wh = g_WThi + (size_t)t * HQ * 1280;
    const __nv_bfloat16* wl = g_WTlo + (size_t)t * HQ * 1280;
    uint32_t bbase = base + 32768;
#pragma unroll
    for (int i = 0; i < 8; i++) {          // B: 2048 chunks
        int it = tid + i * 256;
        int split = it >> 10;
        int row = (it >> 3) & 127;
        int ch = it & 7;
        const __nv_bfloat16* sp = (split ? wl : wh) + (size_t)(n0 + row) * 1280 + k0 + ch * 8;
        uint32_t off = (uint32_t)(row * 128 + ch * 16);
        CP16(bbase + split * 16384 + SWZ(off), sp);
    }
}

__global__ __launch_bounds__(256) void k_tc(
    int srcA, int lvl, int n, int off,
    const float* __restrict__ ibox, const float* __restrict__ bn,
    const float* __restrict__ Wb, const float* __restrict__ bb) {
    extern __shared__ __align__(128) char smem[];
    uint32_t sb = smem_u32(smem);
    int tid = threadIdx.x, wid = tid >> 5, lid = tid & 31;
    int wm = wid & 1, wn = wid >> 1;       // 2 x 4 warp grid

    int m0 = blockIdx.y * TMG;
    int total = g_seg[lvl * 4 + 3];
    if (m0 >= total) return;
    int t = (m0 >= g_seg[lvl * 4 + 2]) ? 2 : (m0 >= g_seg[lvl * 4 + 1]) ? 1 : 0;
    int n0 = blockIdx.x * TNG;

    const __nv_bfloat16* srcHi = srcA ? g_hiA : g_hiB;
    const __nv_bfloat16* srcLo = srcA ? g_loA : g_loB;
    __nv_bfloat16* dstHi = srcA ? g_hiB : g_hiA;
    __nv_bfloat16* dstLo = srcA ? g_loB : g_loA;

    int*   s_pr    = (int*)(smem);
    int*   s_ab    = (int*)(smem + 512);
    float* s_wbox  = (float*)(smem + 1024);
    float* s_bbox  = (float*)(smem + 3072);
    float* s_bnode = (float*)(smem + 3584);

    if (tid < TMG) {
        int pr = g_perm[c_pbase[lvl] + m0 + tid];
        s_pr[tid] = pr;
        s_ab[tid] = (pr < 0 ? 0 : pr) * 1280;
    }
    if (tid < 128) {
#pragma unroll
        for (int q = 0; q < 4; q++) s_wbox[q * 128 + tid] = Wb[q * HQ + n0 + tid];
        s_bbox[tid] = bb[n0 + tid];
        s_bnode[tid] = bn[t * HQ + n0 + tid];
    }
    __syncthreads();

    load_stage(sb, 0, 0, t, n0, tid, srcHi, srcLo, s_ab);
    CP_COMMIT();
    load_stage(sb, 1, KC, t, n0, tid, srcHi, srcLo, s_ab);
    CP_COMMIT();

    float acc[4][4][4];
#pragma unroll
    for (int i = 0; i < 4; i++)
#pragma unroll
        for (int j = 0; j < 4; j++)
#pragma unroll
            for (int q = 0; q < 4; q++) acc[i][j][q] = 0.f;

    // ldmatrix lane addressing (logical offsets, swizzled at use)
    int a_lrow = lid & 15;
    int a_lcol = (lid >> 4) & 1;
    int b_nrow = (lid & 7) | ((lid >> 1) & 8);
    int b_kcol = (lid >> 3) & 1;

    int stg = 0;
    for (int s = 0; s < NSTAGE; s++) {
        if (s + 2 < NSTAGE) {
            int ns = stg + 2; if (ns >= 3) ns -= 3;
            load_stage(sb, ns, (s + 2) * KC, t, n0, tid, srcHi, srcLo, s_ab);
        }
        CP_COMMIT();
        CP_WAIT2();
        __syncthreads();

        uint32_t base = sb + 4096 + stg * STAGE_BYTES;
#pragma unroll
        for (int ks = 0; ks < 4; ks++) {
            uint32_t ah[4][4], al[4][4], bh[4][2], bl[4][2];
#pragma unroll
            for (int mt = 0; mt < 4; mt++) {
                uint32_t offA = (uint32_t)((wm * 64 + mt * 16 + a_lrow) * 128 + ks * 32 + a_lcol * 16);
                ldm4(base + SWZ(offA), ah[mt]);
                ldm4(base + 16384 + SWZ(offA), al[mt]);
            }
#pragma unroll
            for (int np = 0; np < 2; np++) {
                uint32_t offB = (uint32_t)((wn * 32 + np * 16 + b_nrow) * 128 + ks * 32 + b_kcol * 16);
                uint32_t r[4];
                ldm4(base + 32768 + SWZ(offB), r);
                bh[2 * np][0] = r[0]; bh[2 * np][1] = r[1];
                bh[2 * np + 1][0] = r[2]; bh[2 * np + 1][1] = r[3];
                ldm4(base + 49152 + SWZ(offB), r);
                bl[2 * np][0] = r[0]; bl[2 * np][1] = r[1];
                bl[2 * np + 1][0] = r[2]; bl[2 * np + 1][1] = r[3];
            }
#pragma unroll
            for (int mt = 0; mt < 4; mt++)
#pragma unroll
                for (int nt = 0; nt < 4; nt++) {
                    mma16816(acc[mt][nt], ah[mt], bh[nt]);
                    mma16816(acc[mt][nt], ah[mt], bl[nt]);
                    mma16816(acc[mt][nt], al[mt], bh[nt]);
                }
        }
        __syncthreads();
        stg++; if (stg >= 3) stg = 0;
    }

    // ---- epilogue ----
    int lq = lid >> 2, lr = (lid & 3) * 2;
#pragma unroll
    for (int mt = 0; mt < 4; mt++) {
#pragma unroll
        for (int h2 = 0; h2 < 2; h2++) {
            int m = wm * 64 + mt * 16 + lq + h2 * 8;
            int pr = s_pr[m];
            if (pr < 0) continue;
            int b = pr / n, j = pr - b * n;
            float4 bx = *(const float4*)(ibox + ((size_t)b * NINT + off + j) * 4);
#pragma unroll
            for (int nt = 0; nt < 4; nt++) {
                int cl = wn * 32 + nt * 8 + lr;
                float o[2];
#pragma unroll
                for (int u = 0; u < 2; u++) {
                    float be = s_bbox[cl + u];
                    be = fmaf(bx.x, s_wbox[cl + u], be);
                    be = fmaf(bx.y, s_wbox[128 + cl + u], be);
                    be = fmaf(bx.z, s_wbox[256 + cl + u], be);
                    be = fmaf(bx.w, s_wbox[384 + cl + u], be);
                    float v = acc[mt][nt][h2 * 2 + u] + s_bnode[cl + u];
                    o[u] = fmaxf(v, 0.f) + fmaxf(be, 0.f);
                }
                __nv_bfloat16 h0, l0, h1, l1;
                split2(o[0], h0, l0);
                split2(o[1], h1, l1);
                uint32_t hp = (uint32_t)__bfloat16_as_ushort(h0) | ((uint32_t)__bfloat16_as_ushort(h1) << 16);
                uint32_t lp = (uint32_t)__bfloat16_as_ushort(l0) | ((uint32_t)__bfloat16_as_ushort(l1) << 16);
                size_t gidx = (size_t)pr * HQ + n0 + cl;
                *(uint32_t*)(dstHi + gidx) = hp;
                *(uint32_t*)(dstLo + gidx) = lp;
            }
        }
    }
}

// ---------------- VAE head ----------------
__global__ void k_head(const float* __restrict__ eps,
                       const float* __restrict__ W1, const float* __restrict__ b1,
                       const float* __restrict__ Wmu, const float* __restrict__ bmu,
                       const float* __restrict__ Wvar, const float* __restrict__ bvar,
                       float* __restrict__ out) {
    int b = blockIdx.x;
    int h = threadIdx.x;
    __shared__ float sroot[HQ];
    __shared__ float senc[HQ];
    sroot[h] = __bfloat162float(g_hiA[b * HQ + h]) + __bfloat162float(g_loA[b * HQ + h]);
    __syncthreads();
    float a = b1[h];
    for (int k = 0; k < HQ; k++) a = fmaf(sroot[k], W1[k * HQ + h], a);
    senc[h] = fmaxf(a, 0.f);
    __syncthreads();
    float mu = bmu[h], lv = bvar[h];
    for (int k = 0; k < HQ; k++) {
        float e = senc[k];
        mu = fmaf(e, Wmu[k * HQ + h], mu);
        lv = fmaf(e, Wvar[k * HQ + h], lv);
    }
    float stdv = expf(0.5f * lv);
    out[b * 2 * HQ + h] = eps[b * HQ + h] * stdv + mu;
    out[b * 2 * HQ + HQ + h] = 1.f + lv - mu * mu - expf(lv);
}

// ---------------- launch ----------------
extern "C" void kernel_launch(void* const* d_in, const int* in_sizes, int n_in,
                              void* d_out, int out_size) {
    const float* leaf_box     = (const float*)d_in[0];
    const float* leaf_sem     = (const float*)d_in[1];
    const float* internal_box = (const float*)d_in[2];
    const int*   node_type    = (const int*)d_in[3];
    const float* eps          = (const float*)d_in[4];
    const float* W_box        = (const float*)d_in[5];
    const float* b_box        = (const float*)d_in[6];
    const float* W_sem        = (const float*)d_in[7];
    const float* b_sem        = (const float*)d_in[8];
    const float* W_node       = (const float*)d_in[9];
    const float* b_node       = (const float*)d_in[10];
    const float* W1           = (const float*)d_in[11];
    const float* b1           = (const float*)d_in[12];
    const float* Wmu          = (const float*)d_in[13];
    const float* bmu          = (const float*)d_in[14];
    const float* Wvar         = (const float*)d_in[15];
    const float* bvar         = (const float*)d_in[16];
    float* out = (float*)d_out;

    cudaFuncSetAttribute(k_tc, cudaFuncAttributeMaxDynamicSharedMemorySize, SMEM_BYTES);

    k_reset<<<(65536 + 255) / 256, 256>>>();
    k_count<<<(62496 + 255) / 256, 256>>>(node_type);
    k_scan<<<1, 32>>>();
    k_scatter<<<(62496 + 255) / 256, 256>>>(node_type);
    k_wt<<<(3 * HQ * 1280 + 255) / 256, 256>>>(W_node);
    k_leaf<<<(BQ * NLEAF + 3) / 4, 256>>>(leaf_box, leaf_sem, W_box, b_box, W_sem, b_sem);

    struct Lv { int srcA, lvl, n, off, gy; };
    const Lv lv[6] = {
        {1, 5, 3125, 781, 394},
        {0, 4,  625, 156,  82},
        {1, 3,  125,  31,  19},
        {0, 2,   25,   6,   7},
        {1, 1,    5,   1,   4},
        {0, 0,    1,   0,   4},
    };
    for (int i = 0; i < 6; i++) {
        dim3 grid(HQ / TNG, lv[i].gy);
        k_tc<<<grid, 256, SMEM_BYTES>>>(lv[i].srcA, lv[i].lvl, lv[i].n, lv[i].off,
                                        internal_box, b_node, W_box, b_box);
    }

    k_head<<<BQ, HQ>>>(eps, W1, b1, Wmu, bmu, Wvar, bvar, out);
}

// round 4
// speedup vs baseline: 2.3519x; 1.2803x over previous
#include <cuda_runtime.h>
#include <cuda_fp16.h>
#include <cstdint>

// ---------------- problem constants ----------------
#define BQ 16
#define HQ 256
#define NLEAF 15625
#define NINT 3906
#define TMG 128
#define TNG 128
#define KC 64
#define NSTAGE 20
#define STAGE_BYTES 49152          // A 16K | Bhi 16K | Blo 16K
#define SMEM_BYTES (4096 + 3 * STAGE_BYTES)

// ---------------- static device scratch ----------------
__device__ __half g_fA[(size_t)BQ * NLEAF * HQ];   // 128 MB
__device__ __half g_fB[BQ * 3125 * HQ];
__device__ __half g_WThi[3 * HQ * 1280];           // [t][n][k]
__device__ __half g_WTlo[3 * HQ * 1280];
__device__ int g_perm[65536];
__device__ int g_count[18];
__device__ int g_cursor[18];
__device__ int g_seg[24];

__constant__ int c_n[6]     = {1, 5, 25, 125, 625, 3125};
__constant__ int c_off[6]   = {0, 1, 6, 31, 156, 781};
__constant__ int c_cumM[7]  = {0, 16, 96, 496, 2496, 12496, 62496};
__constant__ int c_pbase[6] = {0, 512, 1024, 2048, 4608, 15104};

// ---------------- helpers ----------------
__device__ __forceinline__ uint32_t smem_u32(const void* p) {
    uint32_t a;
    asm("{ .reg .u64 t; cvta.to.shared.u64 t, %1; cvt.u32.u64 %0, t; }" : "=r"(a) : "l"(p));
    return a;
}
#define SWZ(x) ((x) ^ (((x) >> 3) & 0x70))

#define CP16(d, s)  asm volatile("cp.async.cg.shared.global [%0], [%1], 16;" :: "r"(d), "l"(s) : "memory")
#define CP_COMMIT() asm volatile("cp.async.commit_group;" ::: "memory")
#define CP_WAIT2()  asm volatile("cp.async.wait_group 2;" ::: "memory")

__device__ __forceinline__ void ldm4(uint32_t addr, uint32_t* r) {
    asm volatile("ldmatrix.sync.aligned.m8n8.x4.shared.b16 {%0,%1,%2,%3}, [%4];"
                 : "=r"(r[0]), "=r"(r[1]), "=r"(r[2]), "=r"(r[3]) : "r"(addr));
}
__device__ __forceinline__ void mma16816(float* c, const uint32_t* a, const uint32_t* b) {
    asm volatile(
        "mma.sync.aligned.m16n8k16.row.col.f32.f16.f16.f32 "
        "{%0,%1,%2,%3}, {%4,%5,%6,%7}, {%8,%9}, {%0,%1,%2,%3};"
        : "+f"(c[0]), "+f"(c[1]), "+f"(c[2]), "+f"(c[3])
        : "r"(a[0]), "r"(a[1]), "r"(a[2]), "r"(a[3]), "r"(b[0]), "r"(b[1]));
}

// ---------------- prep kernels ----------------
__global__ void k_reset() {
    int i = blockIdx.x * blockDim.x + threadIdx.x;
    if (i < 65536) g_perm[i] = -1;
    if (i < 18) { g_count[i] = 0; g_cursor[i] = 0; }
}

__device__ __forceinline__ void decode_row(int r, int& l, int& pr, int& b, int& j) {
    l = 0;
    while (r >= c_cumM[l + 1]) l++;
    pr = r - c_cumM[l];
    int n = c_n[l];
    b = pr / n;
    j = pr - b * n;
}

__global__ void k_count(const int* __restrict__ nt) {
    __shared__ int sc[18];
    int tid = threadIdx.x;
    if (tid < 18) sc[tid] = 0;
    __syncthreads();
    int r = blockIdx.x * blockDim.x + tid;
    if (r < 62496) {
        int l, pr, b, j;
        decode_row(r, l, pr, b, j);
        int t = nt[b * NINT + c_off[l] + j];
        atomicAdd(&sc[l * 3 + t], 1);
    }
    __syncthreads();
    if (tid < 18 && sc[tid]) atomicAdd(&g_count[tid], sc[tid]);
}

__global__ void k_scan() {
    if (threadIdx.x == 0) {
        for (int l = 0; l < 6; l++) {
            int base = 0;
            for (int t = 0; t < 3; t++) {
                g_seg[l * 4 + t] = base;
                base += ((g_count[l * 3 + t] + TMG - 1) / TMG) * TMG;
            }
            g_seg[l * 4 + 3] = base;
        }
    }
}

__global__ void k_scatter(const int* __restrict__ nt) {
    __shared__ int sc[18], sbase[18];
    int tid = threadIdx.x;
    if (tid < 18) sc[tid] = 0;
    __syncthreads();
    int r = blockIdx.x * blockDim.x + tid;
    int lt = -1, lpos = 0, l = 0, pr = 0;
    if (r < 62496) {
        int b, j;
        decode_row(r, l, pr, b, j);
        int t = nt[b * NINT + c_off[l] + j];
        lt = l * 3 + t;
        lpos = atomicAdd(&sc[lt], 1);
    }
    __syncthreads();
    if (tid < 18 && sc[tid]) sbase[tid] = atomicAdd(&g_cursor[tid], sc[tid]);
    __syncthreads();
    if (lt >= 0) {
        int t = lt - l * 3;
        g_perm[c_pbase[l] + g_seg[l * 4 + t] + sbase[lt] + lpos] = pr;
    }
}

// W_node (3,1280,256) -> [t][n][k] split fp16 hi/lo
__global__ void k_wt(const float* __restrict__ Wn) {
    int i = blockIdx.x * blockDim.x + threadIdx.x;
    if (i >= 3 * HQ * 1280) return;
    int k = i % 1280;
    int r = i / 1280;
    int nn = r % HQ;
    int t = r / HQ;
    float x = Wn[((size_t)t * 1280 + k) * HQ + nn];
    __half h = __float2half(x);
    __half l = __float2half(x - __half2float(h));
    g_WThi[i] = h;
    g_WTlo[i] = l;
}

// ---------------- leaf encoder ----------------
__global__ __launch_bounds__(256) void k_leaf(
    const float* __restrict__ lbox, const float* __restrict__ lsem,
    const float* __restrict__ Wb, const float* __restrict__ bb,
    const float* __restrict__ Ws, const float* __restrict__ bs) {
    __shared__ float sbox[4][4];
    __shared__ float ssem[4][16];
    int tid = threadIdx.x;
    long row0 = (long)blockIdx.x * 4;
    if (tid < 16) sbox[tid >> 2][tid & 3] = lbox[row0 * 4 + tid];
    if (tid < 64) ssem[tid >> 4][tid & 15] = lsem[row0 * 16 + tid];
    __syncthreads();
    int r = tid >> 6;
    int c = (tid & 63) * 4;
    long row = row0 + r;
    float4 a = *(const float4*)(bb + c);
    float acc[4] = {a.x, a.y, a.z, a.w};
#pragma unroll
    for (int q = 0; q < 4; q++) {
        float4 w = *(const float4*)(Wb + q * HQ + c);
        float x = sbox[r][q];
        acc[0] = fmaf(x, w.x, acc[0]); acc[1] = fmaf(x, w.y, acc[1]);
        acc[2] = fmaf(x, w.z, acc[2]); acc[3] = fmaf(x, w.w, acc[3]);
    }
    float4 a2 = *(const float4*)(bs + c);
    float acs[4] = {a2.x, a2.y, a2.z, a2.w};
#pragma unroll
    for (int q = 0; q < 16; q++) {
        float4 w = *(const float4*)(Ws + q * HQ + c);
        float x = ssem[r][q];
        acs[0] = fmaf(x, w.x, acs[0]); acs[1] = fmaf(x, w.y, acs[1]);
        acs[2] = fmaf(x, w.z, acs[2]); acs[3] = fmaf(x, w.w, acs[3]);
    }
    uint32_t p[2];
#pragma unroll
    for (int i = 0; i < 4; i += 2) {
        float v0 = fmaxf(acc[i], 0.f) + fmaxf(acs[i], 0.f);
        float v1 = fmaxf(acc[i + 1], 0.f) + fmaxf(acs[i + 1], 0.f);
        __half2 h2 = __floats2half2_rn(v0, v1);
        p[i >> 1] = *(uint32_t*)&h2;
    }
    *(uint2*)(g_fA + row * HQ + c) = make_uint2(p[0], p[1]);
}

// ---------------- mma.sync grouped GEMM (fp16, 2-product) ----------------
// smem: 0 s_pr[128] | 512 s_ab[128] | 1024 wbox[4*128]f | 3072 bbox[128]f |
//       3584 bnode[128]f | 4096 + stg*48K: {A 16K | Bhi 16K | Blo 16K}
__device__ __forceinline__ void load_stage(
    uint32_t sb, int stg, int k0, int t, int n0, int tid,
    const __half* __restrict__ src, const int* __restrict__ s_ab) {
    uint32_t base = sb + 4096 + stg * STAGE_BYTES;
#pragma unroll
    for (int i = 0; i < 4; i++) {          // A: 1024 chunks of 16B
        int it = tid + i * 256;
        int row = (it >> 3) & 127;
        int ch = it & 7;
        const __half* sp = src + (size_t)s_ab[row] + k0 + ch * 8;
        uint32_t off = (uint32_t)(row * 128 + ch * 16);
        CP16(base + SWZ(off), sp);
    }
    const __half* wh = g_WThi + (size_t)t * HQ * 1280;
    const __half* wl = g_WTlo + (size_t)t * HQ * 1280;
    uint32_t bbase = base + 16384;
#pragma unroll
    for (int i = 0; i < 8; i++) {          // B: hi 1024 + lo 1024 chunks
        int it = tid + i * 256;
        int split = it >> 10;
        int row = (it >> 3) & 127;
        int ch = it & 7;
        const __half* sp = (split ? wl : wh) + (size_t)(n0 + row) * 1280 + k0 + ch * 8;
        uint32_t off = (uint32_t)(row * 128 + ch * 16);
        CP16(bbase + split * 16384 + SWZ(off), sp);
    }
}

__global__ __launch_bounds__(256) void k_tc(
    int srcA, int lvl, int n, int off,
    const float* __restrict__ ibox, const float* __restrict__ bn,
    const float* __restrict__ Wb, const float* __restrict__ bb) {
    extern __shared__ __align__(128) char smem[];
    uint32_t sb = smem_u32(smem);
    int tid = threadIdx.x, wid = tid >> 5, lid = tid & 31;
    int wm = wid & 1, wn = wid >> 1;       // 2 x 4 warp grid

    int m0 = blockIdx.y * TMG;
    int total = g_seg[lvl * 4 + 3];
    if (m0 >= total) return;
    int t = (m0 >= g_seg[lvl * 4 + 2]) ? 2 : (m0 >= g_seg[lvl * 4 + 1]) ? 1 : 0;
    int n0 = blockIdx.x * TNG;

    const __half* src = srcA ? g_fA : g_fB;
    __half* dst = srcA ? g_fB : g_fA;

    int*   s_pr    = (int*)(smem);
    int*   s_ab    = (int*)(smem + 512);
    float* s_wbox  = (float*)(smem + 1024);
    float* s_bbox  = (float*)(smem + 3072);
    float* s_bnode = (float*)(smem + 3584);

    if (tid < TMG) {
        int pr = g_perm[c_pbase[lvl] + m0 + tid];
        s_pr[tid] = pr;
        s_ab[tid] = (pr < 0 ? 0 : pr) * 1280;
    }
    if (tid < 128) {
#pragma unroll
        for (int q = 0; q < 4; q++) s_wbox[q * 128 + tid] = Wb[q * HQ + n0 + tid];
        s_bbox[tid] = bb[n0 + tid];
        s_bnode[tid] = bn[t * HQ + n0 + tid];
    }
    __syncthreads();

    load_stage(sb, 0, 0, t, n0, tid, src, s_ab);
    CP_COMMIT();
    load_stage(sb, 1, KC, t, n0, tid, src, s_ab);
    CP_COMMIT();

    float acc[4][4][4];
#pragma unroll
    for (int i = 0; i < 4; i++)
#pragma unroll
        for (int j = 0; j < 4; j++)
#pragma unroll
            for (int q = 0; q < 4; q++) acc[i][j][q] = 0.f;

    int a_lrow = lid & 15;
    int a_lcol = (lid >> 4) & 1;
    int b_nrow = (lid & 7) | ((lid >> 1) & 8);
    int b_kcol = (lid >> 3) & 1;

    int stg = 0;
    for (int s = 0; s < NSTAGE; s++) {
        if (s + 2 < NSTAGE) {
            int ns = stg + 2; if (ns >= 3) ns -= 3;
            load_stage(sb, ns, (s + 2) * KC, t, n0, tid, src, s_ab);
        }
        CP_COMMIT();
        CP_WAIT2();
        __syncthreads();

        uint32_t base = sb + 4096 + stg * STAGE_BYTES;
#pragma unroll
        for (int ks = 0; ks < 4; ks++) {
            uint32_t ah[4][4], bh[4][2], bl[4][2];
#pragma unroll
            for (int mt = 0; mt < 4; mt++) {
                uint32_t offA = (uint32_t)((wm * 64 + mt * 16 + a_lrow) * 128 + ks * 32 + a_lcol * 16);
                ldm4(base + SWZ(offA), ah[mt]);
            }
#pragma unroll
            for (int np = 0; np < 2; np++) {
                uint32_t offB = (uint32_t)((wn * 32 + np * 16 + b_nrow) * 128 + ks * 32 + b_kcol * 16);
                uint32_t r[4];
                ldm4(base + 16384 + SWZ(offB), r);
                bh[2 * np][0] = r[0]; bh[2 * np][1] = r[1];
                bh[2 * np + 1][0] = r[2]; bh[2 * np + 1][1] = r[3];
                ldm4(base + 32768 + SWZ(offB), r);
                bl[2 * np][0] = r[0]; bl[2 * np][1] = r[1];
                bl[2 * np + 1][0] = r[2]; bl[2 * np + 1][1] = r[3];
            }
#pragma unroll
            for (int mt = 0; mt < 4; mt++)
#pragma unroll
                for (int nt = 0; nt < 4; nt++) {
                    mma16816(acc[mt][nt], ah[mt], bh[nt]);
                    mma16816(acc[mt][nt], ah[mt], bl[nt]);
                }
        }
        __syncthreads();
        stg++; if (stg >= 3) stg = 0;
    }

    // ---- epilogue ----
    int lq = lid >> 2, lr = (lid & 3) * 2;
#pragma unroll
    for (int mt = 0; mt < 4; mt++) {
#pragma unroll
        for (int h2 = 0; h2 < 2; h2++) {
            int m = wm * 64 + mt * 16 + lq + h2 * 8;
            int pr = s_pr[m];
            if (pr < 0) continue;
            int b = pr / n, j = pr - b * n;
            float4 bx = *(const float4*)(ibox + ((size_t)b * NINT + off + j) * 4);
#pragma unroll
            for (int nt = 0; nt < 4; nt++) {
                int cl = wn * 32 + nt * 8 + lr;
                float o[2];
#pragma unroll
                for (int u = 0; u < 2; u++) {
                    float be = s_bbox[cl + u];
                    be = fmaf(bx.x, s_wbox[cl + u], be);
                    be = fmaf(bx.y, s_wbox[128 + cl + u], be);
                    be = fmaf(bx.z, s_wbox[256 + cl + u], be);
                    be = fmaf(bx.w, s_wbox[384 + cl + u], be);
                    float v = acc[mt][nt][h2 * 2 + u] + s_bnode[cl + u];
                    o[u] = fmaxf(v, 0.f) + fmaxf(be, 0.f);
                }
                __half2 hv = __floats2half2_rn(o[0], o[1]);
                *(uint32_t*)(dst + (size_t)pr * HQ + n0 + cl) = *(uint32_t*)&hv;
            }
        }
    }
}

// ---------------- VAE head ----------------
__global__ void k_head(const float* __restrict__ eps,
                       const float* __restrict__ W1, const float* __restrict__ b1,
                       const float* __restrict__ Wmu, const float* __restrict__ bmu,
                       const float* __restrict__ Wvar, const float* __restrict__ bvar,
                       float* __restrict__ out) {
    int b = blockIdx.x;
    int h = threadIdx.x;
    __shared__ float sroot[HQ];
    __shared__ float senc[HQ];
    sroot[h] = __half2float(g_fA[b * HQ + h]);
    __syncthreads();
    float a = b1[h];
    for (int k = 0; k < HQ; k++) a = fmaf(sroot[k], W1[k * HQ + h], a);
    senc[h] = fmaxf(a, 0.f);
    __syncthreads();
    float mu = bmu[h], lv = bvar[h];
    for (int k = 0; k < HQ; k++) {
        float e = senc[k];
        mu = fmaf(e, Wmu[k * HQ + h], mu);
        lv = fmaf(e, Wvar[k * HQ + h], lv);
    }
    float stdv = expf(0.5f * lv);
    out[b * 2 * HQ + h] = eps[b * HQ + h] * stdv + mu;
    out[b * 2 * HQ + HQ + h] = 1.f + lv - mu * mu - expf(lv);
}

// ---------------- launch ----------------
extern "C" void kernel_launch(void* const* d_in, const int* in_sizes, int n_in,
                              void* d_out, int out_size) {
    const float* leaf_box     = (const float*)d_in[0];
    const float* leaf_sem     = (const float*)d_in[1];
    const float* internal_box = (const float*)d_in[2];
    const int*   node_type    = (const int*)d_in[3];
    const float* eps          = (const float*)d_in[4];
    const float* W_box        = (const float*)d_in[5];
    const float* b_box        = (const float*)d_in[6];
    const float* W_sem        = (const float*)d_in[7];
    const float* b_sem        = (const float*)d_in[8];
    const float* W_node       = (const float*)d_in[9];
    const float* b_node       = (const float*)d_in[10];
    const float* W1           = (const float*)d_in[11];
    const float* b1           = (const float*)d_in[12];
    const float* Wmu          = (const float*)d_in[13];
    const float* bmu          = (const float*)d_in[14];
    const float* Wvar         = (const float*)d_in[15];
    const float* bvar         = (const float*)d_in[16];
    float* out = (float*)d_out;

    cudaFuncSetAttribute(k_tc, cudaFuncAttributeMaxDynamicSharedMemorySize, SMEM_BYTES);

    k_reset<<<(65536 + 255) / 256, 256>>>();
    k_count<<<(62496 + 255) / 256, 256>>>(node_type);
    k_scan<<<1, 32>>>();
    k_scatter<<<(62496 + 255) / 256, 256>>>(node_type);
    k_wt<<<(3 * HQ * 1280 + 255) / 256, 256>>>(W_node);
    k_leaf<<<(BQ * NLEAF + 3) / 4, 256>>>(leaf_box, leaf_sem, W_box, b_box, W_sem, b_sem);

    struct Lv { int srcA, lvl, n, off, gy; };
    const Lv lv[6] = {
        {1, 5, 3125, 781, 394},
        {0, 4,  625, 156,  82},
        {1, 3,  125,  31,  19},
        {0, 2,   25,   6,   7},
        {1, 1,    5,   1,   4},
        {0, 0,    1,   0,   4},
    };
    for (int i = 0; i < 6; i++) {
        dim3 grid(HQ / TNG, lv[i].gy);
        k_tc<<<grid, 256, SMEM_BYTES>>>(lv[i].srcA, lv[i].lvl, lv[i].n, lv[i].off,
                                        internal_box, b_node, W_box, b_box);
    }

    k_head<<<BQ, HQ>>>(eps, W1, b1, Wmu, bmu, Wvar, bvar, out);
}

// round 5
// speedup vs baseline: 3.2824x; 1.3956x over previous
#include <cuda_runtime.h>
#include <cuda_fp16.h>
#include <cstdint>

// ---------------- problem constants ----------------
#define BQ 16
#define HQ 256
#define NLEAF 15625
#define NINT 3906
#define TMG 128
#define TNG 128
#define KC 64
#define NSTAGE 20
#define STAGE_BYTES 32768          // A 16K | B 16K
#define SMEM_BYTES (4096 + 3 * STAGE_BYTES)

// ---------------- static device scratch ----------------
__device__ __half g_fA[(size_t)BQ * NLEAF * HQ];   // 128 MB
__device__ __half g_fB[BQ * 3125 * HQ];
__device__ __half g_WT[3 * HQ * 1280];             // [t][n][k] fp16
__device__ int g_perm[65536];
__device__ int g_count[18];
__device__ int g_cursor[18];
__device__ int g_seg[24];

__constant__ int c_n[6]     = {1, 5, 25, 125, 625, 3125};
__constant__ int c_off[6]   = {0, 1, 6, 31, 156, 781};
__constant__ int c_cumM[7]  = {0, 16, 96, 496, 2496, 12496, 62496};
__constant__ int c_pbase[6] = {0, 512, 1024, 2048, 4608, 15104};

// ---------------- helpers ----------------
__device__ __forceinline__ uint32_t smem_u32(const void* p) {
    uint32_t a;
    asm("{ .reg .u64 t; cvta.to.shared.u64 t, %1; cvt.u32.u64 %0, t; }" : "=r"(a) : "l"(p));
    return a;
}
#define SWZ(x) ((x) ^ (((x) >> 3) & 0x70))

#define CP16(d, s)  asm volatile("cp.async.cg.shared.global [%0], [%1], 16;" :: "r"(d), "l"(s) : "memory")
#define CP_COMMIT() asm volatile("cp.async.commit_group;" ::: "memory")
#define CP_WAIT2()  asm volatile("cp.async.wait_group 2;" ::: "memory")

__device__ __forceinline__ void ldm4(uint32_t addr, uint32_t* r) {
    asm volatile("ldmatrix.sync.aligned.m8n8.x4.shared.b16 {%0,%1,%2,%3}, [%4];"
                 : "=r"(r[0]), "=r"(r[1]), "=r"(r[2]), "=r"(r[3]) : "r"(addr));
}
__device__ __forceinline__ void mma16816(float* c, const uint32_t* a, const uint32_t* b) {
    asm volatile(
        "mma.sync.aligned.m16n8k16.row.col.f32.f16.f16.f32 "
        "{%0,%1,%2,%3}, {%4,%5,%6,%7}, {%8,%9}, {%0,%1,%2,%3};"
        : "+f"(c[0]), "+f"(c[1]), "+f"(c[2]), "+f"(c[3])
        : "r"(a[0]), "r"(a[1]), "r"(a[2]), "r"(a[3]), "r"(b[0]), "r"(b[1]));
}

// ---------------- prep kernels ----------------
__global__ void k_reset() {
    int i = blockIdx.x * blockDim.x + threadIdx.x;
    if (i < 65536) g_perm[i] = -1;
    if (i < 18) { g_count[i] = 0; g_cursor[i] = 0; }
}

__device__ __forceinline__ void decode_row(int r, int& l, int& pr, int& b, int& j) {
    l = 0;
    while (r >= c_cumM[l + 1]) l++;
    pr = r - c_cumM[l];
    int n = c_n[l];
    b = pr / n;
    j = pr - b * n;
}

__global__ void k_count(const int* __restrict__ nt) {
    __shared__ int sc[18];
    int tid = threadIdx.x;
    if (tid < 18) sc[tid] = 0;
    __syncthreads();
    int r = blockIdx.x * blockDim.x + tid;
    if (r < 62496) {
        int l, pr, b, j;
        decode_row(r, l, pr, b, j);
        int t = nt[b * NINT + c_off[l] + j];
        atomicAdd(&sc[l * 3 + t], 1);
    }
    __syncthreads();
    if (tid < 18 && sc[tid]) atomicAdd(&g_count[tid], sc[tid]);
}

__global__ void k_scan() {
    if (threadIdx.x == 0) {
        for (int l = 0; l < 6; l++) {
            int base = 0;
            for (int t = 0; t < 3; t++) {
                g_seg[l * 4 + t] = base;
                base += ((g_count[l * 3 + t] + TMG - 1) / TMG) * TMG;
            }
            g_seg[l * 4 + 3] = base;
        }
    }
}

__global__ void k_scatter(const int* __restrict__ nt) {
    __shared__ int sc[18], sbase[18];
    int tid = threadIdx.x;
    if (tid < 18) sc[tid] = 0;
    __syncthreads();
    int r = blockIdx.x * blockDim.x + tid;
    int lt = -1, lpos = 0, l = 0, pr = 0;
    if (r < 62496) {
        int b, j;
        decode_row(r, l, pr, b, j);
        int t = nt[b * NINT + c_off[l] + j];
        lt = l * 3 + t;
        lpos = atomicAdd(&sc[lt], 1);
    }
    __syncthreads();
    if (tid < 18 && sc[tid]) sbase[tid] = atomicAdd(&g_cursor[tid], sc[tid]);
    __syncthreads();
    if (lt >= 0) {
        int t = lt - l * 3;
        g_perm[c_pbase[l] + g_seg[l * 4 + t] + sbase[lt] + lpos] = pr;
    }
}

// W_node (3,1280,256) -> [t][n][k] fp16
__global__ void k_wt(const float* __restrict__ Wn) {
    int i = blockIdx.x * blockDim.x + threadIdx.x;
    if (i >= 3 * HQ * 1280) return;
    int k = i % 1280;
    int r = i / 1280;
    int nn = r % HQ;
    int t = r / HQ;
    g_WT[i] = __float2half(Wn[((size_t)t * 1280 + k) * HQ + nn]);
}

// ---------------- leaf encoder ----------------
__global__ __launch_bounds__(256) void k_leaf(
    const float* __restrict__ lbox, const float* __restrict__ lsem,
    const float* __restrict__ Wb, const float* __restrict__ bb,
    const float* __restrict__ Ws, const float* __restrict__ bs) {
    __shared__ float sbox[4][4];
    __shared__ float ssem[4][16];
    int tid = threadIdx.x;
    long row0 = (long)blockIdx.x * 4;
    if (tid < 16) sbox[tid >> 2][tid & 3] = lbox[row0 * 4 + tid];
    if (tid < 64) ssem[tid >> 4][tid & 15] = lsem[row0 * 16 + tid];
    __syncthreads();
    int r = tid >> 6;
    int c = (tid & 63) * 4;
    long row = row0 + r;
    float4 a = *(const float4*)(bb + c);
    float acc[4] = {a.x, a.y, a.z, a.w};
#pragma unroll
    for (int q = 0; q < 4; q++) {
        float4 w = *(const float4*)(Wb + q * HQ + c);
        float x = sbox[r][q];
        acc[0] = fmaf(x, w.x, acc[0]); acc[1] = fmaf(x, w.y, acc[1]);
        acc[2] = fmaf(x, w.z, acc[2]); acc[3] = fmaf(x, w.w, acc[3]);
    }
    float4 a2 = *(const float4*)(bs + c);
    float acs[4] = {a2.x, a2.y, a2.z, a2.w};
#pragma unroll
    for (int q = 0; q < 16; q++) {
        float4 w = *(const float4*)(Ws + q * HQ + c);
        float x = ssem[r][q];
        acs[0] = fmaf(x, w.x, acs[0]); acs[1] = fmaf(x, w.y, acs[1]);
        acs[2] = fmaf(x, w.z, acs[2]); acs[3] = fmaf(x, w.w, acs[3]);
    }
    uint32_t p[2];
#pragma unroll
    for (int i = 0; i < 4; i += 2) {
        float v0 = fmaxf(acc[i], 0.f) + fmaxf(acs[i], 0.f);
        float v1 = fmaxf(acc[i + 1], 0.f) + fmaxf(acs[i + 1], 0.f);
        __half2 h2 = __floats2half2_rn(v0, v1);
        p[i >> 1] = *(uint32_t*)&h2;
    }
    *(uint2*)(g_fA + row * HQ + c) = make_uint2(p[0], p[1]);
}

// ---------------- mma.sync grouped GEMM (fp16, single product) ----------------
// smem: 0 s_pr[128] | 512 s_ab[128] | 1024 wbox[4*128]f | 3072 bbox[128]f |
//       3584 bnode[128]f | 4096 + stg*32K: {A 16K | B 16K}
__device__ __forceinline__ void load_stage(
    uint32_t sb, int stg, int k0, int t, int n0, int tid,
    const __half* __restrict__ src, const int* __restrict__ s_ab) {
    uint32_t base = sb + 4096 + stg * STAGE_BYTES;
#pragma unroll
    for (int i = 0; i < 4; i++) {          // A: 1024 chunks of 16B
        int it = tid + i * 256;
        int row = (it >> 3) & 127;
        int ch = it & 7;
        const __half* sp = src + (size_t)s_ab[row] + k0 + ch * 8;
        uint32_t off = (uint32_t)(row * 128 + ch * 16);
        CP16(base + SWZ(off), sp);
    }
    const __half* wh = g_WT + (size_t)t * HQ * 1280;
    uint32_t bbase = base + 16384;
#pragma unroll
    for (int i = 0; i < 4; i++) {          // B: 1024 chunks
        int it = tid + i * 256;
        int row = (it >> 3) & 127;
        int ch = it & 7;
        const __half* sp = wh + (size_t)(n0 + row) * 1280 + k0 + ch * 8;
        uint32_t off = (uint32_t)(row * 128 + ch * 16);
        CP16(bbase + SWZ(off), sp);
    }
}

__global__ __launch_bounds__(256, 2) void k_tc(
    int srcA, int lvl, int n, int off,
    const float* __restrict__ ibox, const float* __restrict__ bn,
    const float* __restrict__ Wb, const float* __restrict__ bb) {
    extern __shared__ __align__(128) char smem[];
    uint32_t sb = smem_u32(smem);
    int tid = threadIdx.x, wid = tid >> 5, lid = tid & 31;
    int wm = wid & 1, wn = wid >> 1;       // 2 x 4 warp grid

    int m0 = blockIdx.y * TMG;
    int total = g_seg[lvl * 4 + 3];
    if (m0 >= total) return;
    int t = (m0 >= g_seg[lvl * 4 + 2]) ? 2 : (m0 >= g_seg[lvl * 4 + 1]) ? 1 : 0;
    int n0 = blockIdx.x * TNG;

    const __half* src = srcA ? g_fA : g_fB;
    __half* dst = srcA ? g_fB : g_fA;

    int*   s_pr    = (int*)(smem);
    int*   s_ab    = (int*)(smem + 512);
    float* s_wbox  = (float*)(smem + 1024);
    float* s_bbox  = (float*)(smem + 3072);
    float* s_bnode = (float*)(smem + 3584);

    if (tid < TMG) {
        int pr = g_perm[c_pbase[lvl] + m0 + tid];
        s_pr[tid] = pr;
        s_ab[tid] = (pr < 0 ? 0 : pr) * 1280;
    }
    if (tid < 128) {
#pragma unroll
        for (int q = 0; q < 4; q++) s_wbox[q * 128 + tid] = Wb[q * HQ + n0 + tid];
        s_bbox[tid] = bb[n0 + tid];
        s_bnode[tid] = bn[t * HQ + n0 + tid];
    }
    __syncthreads();

    load_stage(sb, 0, 0, t, n0, tid, src, s_ab);
    CP_COMMIT();
    load_stage(sb, 1, KC, t, n0, tid, src, s_ab);
    CP_COMMIT();

    float acc[4][4][4];
#pragma unroll
    for (int i = 0; i < 4; i++)
#pragma unroll
        for (int j = 0; j < 4; j++)
#pragma unroll
            for (int q = 0; q < 4; q++) acc[i][j][q] = 0.f;

    int a_lrow = lid & 15;
    int a_lcol = (lid >> 4) & 1;
    int b_nrow = (lid & 7) | ((lid >> 1) & 8);
    int b_kcol = (lid >> 3) & 1;

    int stg = 0;
    for (int s = 0; s < NSTAGE; s++) {
        if (s + 2 < NSTAGE) {
            int ns = stg + 2; if (ns >= 3) ns -= 3;
            load_stage(sb, ns, (s + 2) * KC, t, n0, tid, src, s_ab);
        }
        CP_COMMIT();
        CP_WAIT2();
        __syncthreads();

        uint32_t base = sb + 4096 + stg * STAGE_BYTES;
#pragma unroll
        for (int ks = 0; ks < 4; ks++) {
            uint32_t ah[4][4], bh[4][2];
#pragma unroll
            for (int mt = 0; mt < 4; mt++) {
                uint32_t offA = (uint32_t)((wm * 64 + mt * 16 + a_lrow) * 128 + ks * 32 + a_lcol * 16);
                ldm4(base + SWZ(offA), ah[mt]);
            }
#pragma unroll
            for (int np = 0; np < 2; np++) {
                uint32_t offB = (uint32_t)((wn * 32 + np * 16 + b_nrow) * 128 + ks * 32 + b_kcol * 16);
                uint32_t r[4];
                ldm4(base + 16384 + SWZ(offB), r);
                bh[2 * np][0] = r[0]; bh[2 * np][1] = r[1];
                bh[2 * np + 1][0] = r[2]; bh[2 * np + 1][1] = r[3];
            }
#pragma unroll
            for (int mt = 0; mt < 4; mt++)
#pragma unroll
                for (int nt = 0; nt < 4; nt++)
                    mma16816(acc[mt][nt], ah[mt], bh[nt]);
        }
        __syncthreads();
        stg++; if (stg >= 3) stg = 0;
    }

    // ---- epilogue ----
    int lq = lid >> 2, lr = (lid & 3) * 2;
#pragma unroll
    for (int mt = 0; mt < 4; mt++) {
#pragma unroll
        for (int h2 = 0; h2 < 2; h2++) {
            int m = wm * 64 + mt * 16 + lq + h2 * 8;
            int pr = s_pr[m];
            if (pr < 0) continue;
            int b = pr / n, j = pr - b * n;
            float4 bx = *(const float4*)(ibox + ((size_t)b * NINT + off + j) * 4);
#pragma unroll
            for (int nt = 0; nt < 4; nt++) {
                int cl = wn * 32 + nt * 8 + lr;
                float o[2];
#pragma unroll
                for (int u = 0; u < 2; u++) {
                    float be = s_bbox[cl + u];
                    be = fmaf(bx.x, s_wbox[cl + u], be);
                    be = fmaf(bx.y, s_wbox[128 + cl + u], be);
                    be = fmaf(bx.z, s_wbox[256 + cl + u], be);
                    be = fmaf(bx.w, s_wbox[384 + cl + u], be);
                    float v = acc[mt][nt][h2 * 2 + u] + s_bnode[cl + u];
                    o[u] = fmaxf(v, 0.f) + fmaxf(be, 0.f);
                }
                __half2 hv = __floats2half2_rn(o[0], o[1]);
                *(uint32_t*)(dst + (size_t)pr * HQ + n0 + cl) = *(uint32_t*)&hv;
            }
        }
    }
}

// ---------------- VAE head ----------------
__global__ void k_head(const float* __restrict__ eps,
                       const float* __restrict__ W1, const float* __restrict__ b1,
                       const float* __restrict__ Wmu, const float* __restrict__ bmu,
                       const float* __restrict__ Wvar, const float* __restrict__ bvar,
                       float* __restrict__ out) {
    int b = blockIdx.x;
    int h = threadIdx.x;
    __shared__ float sroot[HQ];
    __shared__ float senc[HQ];
    sroot[h] = __half2float(g_fA[b * HQ + h]);
    __syncthreads();
    float a = b1[h];
    for (int k = 0; k < HQ; k++) a = fmaf(sroot[k], W1[k * HQ + h], a);
    senc[h] = fmaxf(a, 0.f);
    __syncthreads();
    float mu = bmu[h], lv = bvar[h];
    for (int k = 0; k < HQ; k++) {
        float e = senc[k];
        mu = fmaf(e, Wmu[k * HQ + h], mu);
        lv = fmaf(e, Wvar[k * HQ + h], lv);
    }
    float stdv = expf(0.5f * lv);
    out[b * 2 * HQ + h] = eps[b * HQ + h] * stdv + mu;
    out[b * 2 * HQ + HQ + h] = 1.f + lv - mu * mu - expf(lv);
}

// ---------------- launch ----------------
extern "C" void kernel_launch(void* const* d_in, const int* in_sizes, int n_in,
                              void* d_out, int out_size) {
    const float* leaf_box     = (const float*)d_in[0];
    const float* leaf_sem     = (const float*)d_in[1];
    const float* internal_box = (const float*)d_in[2];
    const int*   node_type    = (const int*)d_in[3];
    const float* eps          = (const float*)d_in[4];
    const float* W_box        = (const float*)d_in[5];
    const float* b_box        = (const float*)d_in[6];
    const float* W_sem        = (const float*)d_in[7];
    const float* b_sem        = (const float*)d_in[8];
    const float* W_node       = (const float*)d_in[9];
    const float* b_node       = (const float*)d_in[10];
    const float* W1           = (const float*)d_in[11];
    const float* b1           = (const float*)d_in[12];
    const float* Wmu          = (const float*)d_in[13];
    const float* bmu          = (const float*)d_in[14];
    const float* Wvar         = (const float*)d_in[15];
    const float* bvar         = (const float*)d_in[16];
    float* out = (float*)d_out;

    cudaFuncSetAttribute(k_tc, cudaFuncAttributeMaxDynamicSharedMemorySize, SMEM_BYTES);

    k_reset<<<(65536 + 255) / 256, 256>>>();
    k_count<<<(62496 + 255) / 256, 256>>>(node_type);
    k_scan<<<1, 32>>>();
    k_scatter<<<(62496 + 255) / 256, 256>>>(node_type);
    k_wt<<<(3 * HQ * 1280 + 255) / 256, 256>>>(W_node);
    k_leaf<<<(BQ * NLEAF + 3) / 4, 256>>>(leaf_box, leaf_sem, W_box, b_box, W_sem, b_sem);

    struct Lv { int srcA, lvl, n, off, gy; };
    const Lv lv[6] = {
        {1, 5, 3125, 781, 394},
        {0, 4,  625, 156,  82},
        {1, 3,  125,  31,  19},
        {0, 2,   25,   6,   7},
        {1, 1,    5,   1,   4},
        {0, 0,    1,   0,   4},
    };
    for (int i = 0; i < 6; i++) {
        dim3 grid(HQ / TNG, lv[i].gy);
        k_tc<<<grid, 256, SMEM_BYTES>>>(lv[i].srcA, lv[i].lvl, lv[i].n, lv[i].off,
                                        internal_box, b_node, W_box, b_box);
    }

    k_head<<<BQ, HQ>>>(eps, W1, b1, Wmu, bmu, Wvar, bvar, out);
}